// round 3
// baseline (speedup 1.0000x reference)
#include <cuda_runtime.h>
#include <stdint.h>

// Problem constants (fixed-shape problem)
#define NROWS 65536              // 256*256 neurons
#define BATCH 64
#define CAP   1024               // ELL row capacity (corner rows reach ~700 due to clamping)

// ---------------- device scratch (static; no runtime allocation) ----------------
__device__ float  g_xt[NROWS * BATCH];           // x transposed: [N, 64]
__device__ int    g_counts[NROWS];               // per-destination-row edge count
__device__ float2 g_ell[(size_t)NROWS * CAP];    // (value, col-as-bits) per slot

// ---------------- 1. transpose x [64, N] -> xt [N, 64] ----------------
__global__ void transpose_kernel(const float* __restrict__ x) {
    __shared__ float s[32][33];
    int n0 = blockIdx.x * 32;
    int b0 = blockIdx.y * 32;
    int tx = threadIdx.x;       // 0..31
    int ty = threadIdx.y;       // 0..7
#pragma unroll
    for (int k = 0; k < 4; k++) {
        int b = ty + k * 8;
        s[b][tx] = x[(size_t)(b0 + b) * NROWS + n0 + tx];
    }
    __syncthreads();
#pragma unroll
    for (int k = 0; k < 4; k++) {
        int n = ty + k * 8;
        g_xt[(size_t)(n0 + n) * BATCH + b0 + tx] = s[tx][n];
    }
}

// ---------------- 2. zero counts ----------------
__global__ void zero_kernel() {
    int i = blockIdx.x * blockDim.x + threadIdx.x;
    if (i < NROWS) g_counts[i] = 0;
}

// ---------------- 3. scatter edges into ELL (histogram fused into scatter) ----------------
__global__ void scatter_kernel(const int* __restrict__ rows,
                               const int* __restrict__ cols,
                               const float* __restrict__ vals, int nnz) {
    int e = blockIdx.x * blockDim.x + threadIdx.x;
    if (e < nnz) {
        int r = rows[e];
        int pos = atomicAdd(&g_counts[r], 1);
        if (pos < CAP) {
            g_ell[((size_t)r << 10) + pos] =
                make_float2(vals[e], __int_as_float(cols[e]));
        }
    }
}

// ---------------- 4. gather SpMM: out[b, r] = sum_e v_e * xt[col_e][b] ----------------
// Block = 256 threads (8 warps) handles 32 consecutive output rows.
// Warp w handles rows r0 + 4w .. r0 + 4w + 3, INTERLEAVED in the inner loop so
// each chain step issues 4 independent L2 gathers (MLP=4) instead of 1.
// Lane l accumulates batch elements (2l, 2l+1) via one float2 load.
__global__ void __launch_bounds__(256) spmm_kernel(float* __restrict__ out) {
    __shared__ float tile[32 * 65];   // [row_local][b], stride 65 kills bank conflicts
    int t = threadIdx.x;
    int warp = t >> 5;
    int lane = t & 31;
    int r0 = blockIdx.x * 32;
    int rbase = r0 + warp * 4;

    int cnt[4];
    const float2* __restrict__ ell[4];
    int maxc = 0;
#pragma unroll
    for (int k = 0; k < 4; k++) {
        int r = rbase + k;
        int c = g_counts[r];
        cnt[k] = c < CAP ? c : CAP;
        ell[k] = &g_ell[(size_t)r << 10];
        maxc = cnt[k] > maxc ? cnt[k] : maxc;
    }

    float accx[4] = {0.f, 0.f, 0.f, 0.f};
    float accy[4] = {0.f, 0.f, 0.f, 0.f};
    const size_t laneoff = (size_t)(lane << 1);

    for (int i = 0; i < maxc; i++) {
        float2 vc[4];
#pragma unroll
        for (int k = 0; k < 4; k++) {
            // padded iterations: value 0, column 0 (harmless dummy gather)
            vc[k] = (i < cnt[k]) ? __ldg(&ell[k][i])
                                 : make_float2(0.f, __int_as_float(0));
        }
#pragma unroll
        for (int k = 0; k < 4; k++) {
            int c = __float_as_int(vc[k].y);
            const float2 xv = *reinterpret_cast<const float2*>(
                &g_xt[((size_t)c << 6) + laneoff]);   // 4 independent L2 gathers in flight
            accx[k] = fmaf(vc[k].x, xv.x, accx[k]);
            accy[k] = fmaf(vc[k].x, xv.y, accy[k]);
        }
    }

#pragma unroll
    for (int k = 0; k < 4; k++) {
        int row_local = warp * 4 + k;
        tile[row_local * 65 + (lane << 1)]     = accx[k];
        tile[row_local * 65 + (lane << 1) + 1] = accy[k];
    }
    __syncthreads();
#pragma unroll
    for (int k = 0; k < 8; k++) {
        int idx = k * 256 + t;
        int b = idx >> 5;        // 0..63
        int c = idx & 31;        // 0..31
        out[(size_t)b * NROWS + r0 + c] = tile[c * 65 + b];
    }
}

// ---------------- launch ----------------
extern "C" void kernel_launch(void* const* d_in, const int* in_sizes, int n_in,
                              void* d_out, int out_size) {
    const float* x    = (const float*)d_in[0];   // [64, 65536]
    const float* vals = (const float*)d_in[1];   // [NNZ]
    const int*   rows = (const int*)d_in[2];     // [NNZ] int32
    const int*   cols = (const int*)d_in[3];     // [NNZ] int32
    float* out = (float*)d_out;                  // [64, 65536]
    int nnz = in_sizes[1];

    // transpose x -> xt [N, 64]
    {
        dim3 blk(32, 8);
        dim3 grd(NROWS / 32, BATCH / 32);
        transpose_kernel<<<grd, blk>>>(x);
    }
    // ELL build: zero counts, then scatter (histogram fused)
    zero_kernel<<<NROWS / 256, 256>>>();
    scatter_kernel<<<(nnz + 255) / 256, 256>>>(rows, cols, vals, nnz);
    // gather SpMM
    spmm_kernel<<<NROWS / 32, 256>>>(out);
}

// round 4
// speedup vs baseline: 1.5058x; 1.5058x over previous
#include <cuda_runtime.h>
#include <stdint.h>

// Problem constants (fixed-shape problem)
#define NROWS 65536              // 256*256 neurons
#define BATCH 64
#define CAP   1024               // ELL row capacity (corner rows reach ~700 due to clamping)

// ---------------- device scratch (static; no runtime allocation) ----------------
__device__ float  g_xt[NROWS * BATCH];           // x transposed: [N, 64]
__device__ int    g_counts[NROWS];               // per-destination-row edge count
__device__ float2 g_ell[(size_t)NROWS * CAP];    // (value, col-as-bits) per slot

// ---------------- 1. transpose x [64, N] -> xt [N, 64] ----------------
__global__ void transpose_kernel(const float* __restrict__ x) {
    __shared__ float s[32][33];
    int n0 = blockIdx.x * 32;
    int b0 = blockIdx.y * 32;
    int tx = threadIdx.x;       // 0..31
    int ty = threadIdx.y;       // 0..7
#pragma unroll
    for (int k = 0; k < 4; k++) {
        int b = ty + k * 8;
        s[b][tx] = x[(size_t)(b0 + b) * NROWS + n0 + tx];
    }
    __syncthreads();
#pragma unroll
    for (int k = 0; k < 4; k++) {
        int n = ty + k * 8;
        g_xt[(size_t)(n0 + n) * BATCH + b0 + tx] = s[tx][n];
    }
}

// ---------------- 2. zero counts ----------------
__global__ void zero_kernel() {
    int i = blockIdx.x * blockDim.x + threadIdx.x;
    if (i < NROWS) g_counts[i] = 0;
}

// ---------------- 3. scatter edges into ELL (histogram fused into scatter) ----------------
__global__ void scatter_kernel(const int* __restrict__ rows,
                               const int* __restrict__ cols,
                               const float* __restrict__ vals, int nnz) {
    int e = blockIdx.x * blockDim.x + threadIdx.x;
    if (e < nnz) {
        int r = rows[e];
        int pos = atomicAdd(&g_counts[r], 1);
        if (pos < CAP) {
            g_ell[((size_t)r << 10) + pos] =
                make_float2(vals[e], __int_as_float(cols[e]));
        }
    }
}

// ---------------- 4. gather SpMM: out[b, r] = sum_e v_e * xt[col_e][b] ----------------
// Block = 1024 threads = 32 warps; warp w owns row r0 + w.
// ELL edges are loaded LANE-PARALLEL (lane l loads edge j0+l, coalesced 256B),
// then broadcast via __shfl. Gathers are batched in groups of 8 so 8 independent
// L2 loads are in flight before any FMA consumes them (compiler-visible MLP=8).
// Lane l accumulates batch elements (2l, 2l+1). Output staged in smem for
// fully coalesced 128B writes of out[b, r0..r0+31].
__global__ void __launch_bounds__(1024) spmm_kernel(float* __restrict__ out) {
    __shared__ float tile[32 * 65];   // [row_local][b], stride 65 kills bank conflicts
    const int t = threadIdx.x;
    const int warp = t >> 5;
    const int lane = t & 31;
    const int r0 = blockIdx.x * 32;
    const int r = r0 + warp;

    int cnt = g_counts[r];
    if (cnt > CAP) cnt = CAP;
    const float2* __restrict__ ell = &g_ell[(size_t)r << 10];
    const float2* __restrict__ xt2 = (const float2*)g_xt;  // [N][32] float2

    float accx = 0.f, accy = 0.f;

    for (int j0 = 0; j0 < cnt; j0 += 32) {
        // lane-parallel edge fetch; invalid lanes -> (v=0, col=0) dummy
        float2 e = (j0 + lane < cnt) ? __ldg(&ell[j0 + lane])
                                     : make_float2(0.f, __int_as_float(0));
        const float ev = e.x;
        const int   ec = __float_as_int(e.y);
        int m = cnt - j0; if (m > 32) m = 32;

#pragma unroll
        for (int g = 0; g < 4; g++) {
            if (g * 8 >= m) break;          // uniform skip of empty groups
            float  v[8];
            int    c[8];
            float2 xv[8];
#pragma unroll
            for (int u = 0; u < 8; u++) {
                v[u] = __shfl_sync(0xffffffffu, ev, g * 8 + u);
                c[u] = __shfl_sync(0xffffffffu, ec, g * 8 + u);
            }
#pragma unroll
            for (int u = 0; u < 8; u++)     // 8 independent gathers in flight
                xv[u] = __ldg(&xt2[(c[u] << 5) + lane]);
#pragma unroll
            for (int u = 0; u < 8; u++) {
                accx = fmaf(v[u], xv[u].x, accx);
                accy = fmaf(v[u], xv[u].y, accy);
            }
        }
    }

    tile[warp * 65 + (lane << 1)]     = accx;
    tile[warp * 65 + (lane << 1) + 1] = accy;
    __syncthreads();
#pragma unroll
    for (int k = 0; k < 2; k++) {
        int idx = k * 1024 + t;
        int b = idx >> 5;        // 0..63
        int c = idx & 31;        // 0..31
        out[b * NROWS + r0 + c] = tile[c * 65 + b];
    }
}

// ---------------- launch ----------------
extern "C" void kernel_launch(void* const* d_in, const int* in_sizes, int n_in,
                              void* d_out, int out_size) {
    const float* x    = (const float*)d_in[0];   // [64, 65536]
    const float* vals = (const float*)d_in[1];   // [NNZ]
    const int*   rows = (const int*)d_in[2];     // [NNZ] int32
    const int*   cols = (const int*)d_in[3];     // [NNZ] int32
    float* out = (float*)d_out;                  // [64, 65536]
    int nnz = in_sizes[1];

    // transpose x -> xt [N, 64]
    {
        dim3 blk(32, 8);
        dim3 grd(NROWS / 32, BATCH / 32);
        transpose_kernel<<<grd, blk>>>(x);
    }
    // ELL build: zero counts, then scatter (histogram fused)
    zero_kernel<<<NROWS / 256, 256>>>();
    scatter_kernel<<<(nnz + 255) / 256, 256>>>(rows, cols, vals, nnz);
    // gather SpMM
    spmm_kernel<<<NROWS / 32, 1024>>>(out);
}

// round 5
// speedup vs baseline: 1.8020x; 1.1967x over previous
#include <cuda_runtime.h>
#include <stdint.h>

// Problem constants (fixed-shape problem)
#define NROWS 65536              // 256*256 neurons
#define BATCH 64
#define CAP   1024               // ELL row capacity (corner rows reach ~700 due to clamping)

// ---------------- device scratch (static; no runtime allocation) ----------------
__device__ float  g_xt[NROWS * BATCH];           // x transposed: [N, 64]
__device__ int    g_counts[NROWS];               // per-destination-row edge count
__device__ float2 g_ell[(size_t)NROWS * CAP];    // (value, col-as-bits) per slot

// ---------------- 1. transpose x [64, N] -> xt [N, 64]  (+ fused counts zeroing) ----------------
__global__ void transpose_kernel(const float* __restrict__ x) {
    __shared__ float s[32][33];
    int n0 = blockIdx.x * 32;
    int b0 = blockIdx.y * 32;
    int tx = threadIdx.x;       // 0..31
    int ty = threadIdx.y;       // 0..7

    // fused: zero g_counts (first 256 blocks of the y==0 slice cover 65536 ints)
    if (blockIdx.y == 0) {
        int i = blockIdx.x * 256 + ty * 32 + tx;
        if (i < NROWS) g_counts[i] = 0;
    }

#pragma unroll
    for (int k = 0; k < 4; k++) {
        int b = ty + k * 8;
        s[b][tx] = x[(size_t)(b0 + b) * NROWS + n0 + tx];
    }
    __syncthreads();
#pragma unroll
    for (int k = 0; k < 4; k++) {
        int n = ty + k * 8;
        g_xt[(size_t)(n0 + n) * BATCH + b0 + tx] = s[tx][n];
    }
}

// ---------------- 2. scatter edges into ELL (histogram fused into scatter) ----------------
__global__ void scatter_kernel(const int* __restrict__ rows,
                               const int* __restrict__ cols,
                               const float* __restrict__ vals, int nnz) {
    int e = blockIdx.x * blockDim.x + threadIdx.x;
    if (e < nnz) {
        int r = rows[e];
        int pos = atomicAdd(&g_counts[r], 1);
        if (pos < CAP) {
            g_ell[((size_t)r << 10) + pos] =
                make_float2(vals[e], __int_as_float(cols[e]));
        }
    }
}

// ---------------- 3. gather SpMM: out[b, r] = sum_e v_e * xt[col_e][b] ----------------
// Block = 1024 threads = 32 warps; warp w owns row r0 + w.
// TWO edges per gather instruction: a row's 64 batch floats span 16 lanes of
// float4, so lanes 0-15 gather edge 2p and lanes 16-31 gather edge 2p+1 in one
// LDG.128. Edge (v,c) come from a lane-parallel coalesced ELL load, broadcast
// by variable-source shfl. Groups of 4 pairs keep 8 edges (4 LDG.128) in flight.
// Halves are combined with shfl_xor(16) adds at the end.
__global__ void __launch_bounds__(1024) spmm_kernel(float* __restrict__ out) {
    __shared__ float tile[32 * 65];   // [row_local][b], stride 65: conflict-free reads
    const int t = threadIdx.x;
    const int warp = t >> 5;
    const int lane = t & 31;
    const int half = lane >> 4;       // 0: even edges, 1: odd edges
    const int quad = lane & 15;       // batch group: floats quad*4 .. quad*4+3
    const int r0 = blockIdx.x * 32;
    const int r = r0 + warp;

    int cnt = g_counts[r];
    if (cnt > CAP) cnt = CAP;
    const float2* __restrict__ ell = &g_ell[(size_t)r << 10];
    const float4* __restrict__ xt4 = (const float4*)g_xt;   // [N][16] float4

    float4 acc = make_float4(0.f, 0.f, 0.f, 0.f);

    for (int j0 = 0; j0 < cnt; j0 += 32) {
        // lane-parallel edge fetch; invalid lanes -> (v=0, col=0) dummy
        float2 e = (j0 + lane < cnt) ? __ldg(&ell[j0 + lane])
                                     : make_float2(0.f, __int_as_float(0));
        const float ev = e.x;
        const int   ec = __float_as_int(e.y);
        int m = cnt - j0; if (m > 32) m = 32;
        int npairs = (m + 1) >> 1;    // edge pairs in this chunk (<=16)

#pragma unroll
        for (int g = 0; g < 4; g++) {
            if (g * 4 >= npairs) break;   // uniform skip of empty pair-groups
            float  v[4];
            int    c[4];
            float4 xv[4];
#pragma unroll
            for (int u = 0; u < 4; u++) {
                int src = (((g * 4 + u) << 1) + half);   // edge index in chunk
                v[u] = __shfl_sync(0xffffffffu, ev, src);
                c[u] = __shfl_sync(0xffffffffu, ec, src);
            }
#pragma unroll
            for (int u = 0; u < 4; u++)   // 4 LDG.128 = 8 edges in flight
                xv[u] = __ldg(&xt4[(c[u] << 4) + quad]);
#pragma unroll
            for (int u = 0; u < 4; u++) {
                acc.x = fmaf(v[u], xv[u].x, acc.x);
                acc.y = fmaf(v[u], xv[u].y, acc.y);
                acc.z = fmaf(v[u], xv[u].z, acc.z);
                acc.w = fmaf(v[u], xv[u].w, acc.w);
            }
        }
    }

    // combine even-edge and odd-edge halves (lane l and l+16 hold same batch)
    acc.x += __shfl_xor_sync(0xffffffffu, acc.x, 16);
    acc.y += __shfl_xor_sync(0xffffffffu, acc.y, 16);
    acc.z += __shfl_xor_sync(0xffffffffu, acc.z, 16);
    acc.w += __shfl_xor_sync(0xffffffffu, acc.w, 16);

    if (half == 0) {
        int base = warp * 65 + (quad << 2);
        tile[base + 0] = acc.x;
        tile[base + 1] = acc.y;
        tile[base + 2] = acc.z;
        tile[base + 3] = acc.w;
    }
    __syncthreads();
#pragma unroll
    for (int k = 0; k < 2; k++) {
        int idx = k * 1024 + t;
        int b = idx >> 5;        // 0..63
        int c = idx & 31;        // 0..31
        out[b * NROWS + r0 + c] = tile[c * 65 + b];
    }
}

// ---------------- launch ----------------
extern "C" void kernel_launch(void* const* d_in, const int* in_sizes, int n_in,
                              void* d_out, int out_size) {
    const float* x    = (const float*)d_in[0];   // [64, 65536]
    const float* vals = (const float*)d_in[1];   // [NNZ]
    const int*   rows = (const int*)d_in[2];     // [NNZ] int32
    const int*   cols = (const int*)d_in[3];     // [NNZ] int32
    float* out = (float*)d_out;                  // [64, 65536]
    int nnz = in_sizes[1];

    // transpose x -> xt [N, 64]  (also zeroes g_counts)
    {
        dim3 blk(32, 8);
        dim3 grd(NROWS / 32, BATCH / 32);
        transpose_kernel<<<grd, blk>>>(x);
    }
    // ELL build: scatter with fused histogram
    scatter_kernel<<<(nnz + 255) / 256, 256>>>(rows, cols, vals, nnz);
    // gather SpMM
    spmm_kernel<<<NROWS / 32, 1024>>>(out);
}